// round 4
// baseline (speedup 1.0000x reference)
#include <cuda_runtime.h>

#define BATCH 4
#define NPTS  4096
#define KNB   16
#define DPD   128
#define DMD   256
#define ROWS  (BATCH * NPTS)   // 16384

// ---------------- scratch (static device globals; no allocations) ----------------
__device__ float  g_Wc[DPD * 1024];          // [128,1024] = fc1@(wq | wk | wv | wq@fd2^T)
__device__ float  g_bc[1024];
__device__ float  g_Wo[512 * DPD];           // [512,128]  = [fd2@fc2 ; fc2]
__device__ float  g_bo[DPD];                 // fd2b@fc2 + fc2b
__device__ float4 g_pts[ROWS];               // (x,y,z, |xyz|^2)
__device__ int    g_knn[ROWS * KNB];
__device__ float  g_QKV[(size_t)ROWS * 1024];// [16384,1024] (q|k|v|qp)
__device__ float  g_HA[(size_t)ROWS * 512];  // [16384,512]  (hbar|av)

// ---------------- prep kernels ----------------
__global__ __launch_bounds__(256) void prep_wc_k(
    const float* __restrict__ fc1w, const float* __restrict__ fc1b,
    const float* __restrict__ wq,   const float* __restrict__ wk,
    const float* __restrict__ wv)
{
    int t = blockIdx.x * 256 + threadIdx.x;   // 0 .. 128*768-1
    int r = t / 768, c = t % 768;
    const float* w = (c < 256) ? wq : (c < 512) ? wk : wv;
    int cc = c & 255;
    float s = 0.f;
#pragma unroll 4
    for (int m = 0; m < 256; m++)
        s = fmaf(__ldg(fc1w + r * 256 + m), __ldg(w + m * 256 + cc), s);
    g_Wc[r * 1024 + c] = s;
    if (r == 0) {
        float b = 0.f;
#pragma unroll 4
        for (int m = 0; m < 256; m++)
            b = fmaf(__ldg(fc1b + m), __ldg(w + m * 256 + cc), b);
        g_bc[c] = b;
    }
}

// qp block: Wc[:,768+d] = sum_m Wc_q[:,m] * fd2w[d,m]   (row d of fd2w)
__global__ __launch_bounds__(256) void prep_qp_k(const float* __restrict__ fd2w)
{
    int t = blockIdx.x * 256 + threadIdx.x;   // 0 .. 128*256-1
    int r = t >> 8, d = t & 255;
    float s = 0.f;
#pragma unroll 4
    for (int m = 0; m < 256; m++)
        s = fmaf(g_Wc[r * 1024 + m], __ldg(fd2w + d * 256 + m), s);
    g_Wc[r * 1024 + 768 + d] = s;
    if (r == 0) {
        float b = 0.f;
#pragma unroll 4
        for (int m = 0; m < 256; m++)
            b = fmaf(g_bc[m], __ldg(fd2w + d * 256 + m), b);
        g_bc[768 + d] = b;
    }
}

// Wo = [fd2w@fc2w ; fc2w]  [512,128],  bo = fd2b@fc2w + fc2b
__global__ __launch_bounds__(256) void prep_wo_k(
    const float* __restrict__ fd2w, const float* __restrict__ fd2b,
    const float* __restrict__ fc2w, const float* __restrict__ fc2b)
{
    int t = blockIdx.x * 256 + threadIdx.x;   // 0 .. 512*128-1
    int j = t >> 7, c = t & 127;
    float s;
    if (j < 256) {
        s = 0.f;
#pragma unroll 4
        for (int m = 0; m < 256; m++)
            s = fmaf(__ldg(fd2w + j * 256 + m), __ldg(fc2w + m * 128 + c), s);
    } else {
        s = __ldg(fc2w + (j - 256) * 128 + c);
    }
    g_Wo[j * 128 + c] = s;
    if (j == 0) {
        float b = 0.f;
#pragma unroll 4
        for (int m = 0; m < 256; m++)
            b = fmaf(__ldg(fd2b + m), __ldg(fc2w + m * 128 + c), b);
        g_bo[c] = b + __ldg(fc2b + c);
    }
}

__global__ void pack_xyz_k(const float* __restrict__ xyz)
{
    int p = blockIdx.x * 256 + threadIdx.x;   // 16384
    float x = xyz[p * 3], y = xyz[p * 3 + 1], z = xyz[p * 3 + 2];
    float sq = x * x; sq = fmaf(y, y, sq); sq = fmaf(z, z, sq);
    g_pts[p] = make_float4(x, y, z, sq);
}

// ---------------- KNN: warp per query, distributed sorted top-16 ----------------
__global__ __launch_bounds__(256) void knn_kernel()
{
    int p    = (blockIdx.x * 256 + threadIdx.x) >> 5;
    int lane = threadIdx.x & 31;
    int b = p >> 12;
    const float4* bp = g_pts + (b << 12);
    float4 me = __ldg(bp + (p & 4095));
    float qx = me.x, qy = me.y, qz = me.z, qsq = me.w;

    float ld = 3.0e38f;
    int   li = 0;
    float worst = 3.0e38f;

    for (int j0 = 0; j0 < 4096; j0 += 32) {
        float4 o = __ldg(bp + j0 + lane);
        float tt = qx * o.x; tt = fmaf(qy, o.y, tt); tt = fmaf(qz, o.z, tt);
        float d2 = fmaf(-2.f, tt, qsq + o.w);   // exact reference formula
        unsigned ball = __ballot_sync(0xffffffffu, d2 < worst);
        while (ball) {
            int src = __ffs(ball) - 1;
            ball &= ball - 1;
            float v = __shfl_sync(0xffffffffu, d2, src);
            if (v < worst) {
                int vi = j0 + src;
                float pd = __shfl_up_sync(0xffffffffu, ld, 1);
                int   pi = __shfl_up_sync(0xffffffffu, li, 1);
                bool pgt = (lane != 0) && (pd > v);
                if (ld > v) {
                    if (pgt) { ld = pd; li = pi; }
                    else     { ld = v;  li = vi; }
                }
                worst = __shfl_sync(0xffffffffu, ld, 15);
            }
        }
    }
    if (lane < 16) g_knn[p * 16 + lane] = li;
}

// ---------------- SGEMM with packed f32x2 FMA ----------------
// MODE 0: QKV = features @ g_Wc + g_bc             [16384,1024], K=128, lda=128
// MODE 1: OUT = g_HA @ g_Wo + g_bo + features      [16384,128],  K=512, lda=512
//         (stored transposed [B,DP,N])
template<int MODE>
__global__ __launch_bounds__(256) void sgemm_k(
    const float* __restrict__ Aext, const float* __restrict__ addExt,
    float* __restrict__ Cext, int N, int Kd, int lda)
{
    const float* A = (MODE == 0) ? Aext : g_HA;
    const float* B = (MODE == 0) ? g_Wc : g_Wo;
    const float* bias = (MODE == 0) ? g_bc : g_bo;
    float* C = (MODE == 0) ? g_QKV : Cext;

    __shared__ float As[8][128];
    __shared__ float Bs[8][128];
    int tid  = threadIdx.x;
    int brow = blockIdx.y * 128;
    int bcol = blockIdx.x * 128;
    int ar = tid >> 1, ac = (tid & 1) * 4;
    int br = tid >> 5, bc = (tid & 31) * 4;
    int ty = tid >> 4, tx = tid & 15;

    unsigned long long acc2[8][4];   // [i][j-pair], 2 fp32 per entry
#pragma unroll
    for (int i = 0; i < 8; i++)
#pragma unroll
        for (int j = 0; j < 4; j++) acc2[i][j] = 0ull;

    const float* Aptr = A + (size_t)(brow + ar) * lda + ac;
    const float* Bptr = B + (size_t)br * N + bcol + bc;

    for (int k0 = 0; k0 < Kd; k0 += 8) {
        float4 av = *(const float4*)(Aptr + k0);
        float4 bv = *(const float4*)(Bptr + (size_t)k0 * N);
        __syncthreads();
        As[ac + 0][ar] = av.x; As[ac + 1][ar] = av.y;
        As[ac + 2][ar] = av.z; As[ac + 3][ar] = av.w;
        *(float4*)(&Bs[br][bc]) = bv;
        __syncthreads();
#pragma unroll
        for (int kk = 0; kk < 8; kk++) {
            float a8[8];
            *(float4*)(a8)     = *(const float4*)(&As[kk][ty * 8]);
            *(float4*)(a8 + 4) = *(const float4*)(&As[kk][ty * 8 + 4]);
            unsigned long long b2[4];
            *(float4*)(&b2[0]) = *(const float4*)(&Bs[kk][tx * 8]);
            *(float4*)(&b2[2]) = *(const float4*)(&Bs[kk][tx * 8 + 4]);
            unsigned long long a2[8];
#pragma unroll
            for (int i = 0; i < 8; i++)
                asm("mov.b64 %0, {%1, %1};" : "=l"(a2[i]) : "f"(a8[i]));
#pragma unroll
            for (int i = 0; i < 8; i++)
#pragma unroll
                for (int j = 0; j < 4; j++)
                    asm("fma.rn.f32x2 %0, %1, %2, %3;"
                        : "=l"(acc2[i][j])
                        : "l"(a2[i]), "l"(b2[j]), "l"(acc2[i][j]));
        }
    }

    float bb[8];
#pragma unroll
    for (int j = 0; j < 8; j++) bb[j] = bias[bcol + tx * 8 + j];

#pragma unroll
    for (int i = 0; i < 8; i++) {
        int r = brow + ty * 8 + i;
#pragma unroll
        for (int j2 = 0; j2 < 4; j2++) {
            float lo, hi;
            asm("mov.b64 {%0, %1}, %2;" : "=f"(lo), "=f"(hi) : "l"(acc2[i][j2]));
#pragma unroll
            for (int s = 0; s < 2; s++) {
                int j = j2 * 2 + s;
                int c = bcol + tx * 8 + j;
                float v = (s ? hi : lo) + bb[j];
                if (MODE == 1) {
                    v += addExt[(size_t)r * DPD + c];   // + features residual
                    C[(size_t)((r >> 12) * DPD + c) * NPTS + (r & 4095)] = v;  // [B,DP,N]
                } else {
                    C[(size_t)r * 1024 + c] = v;
                }
            }
        }
    }
}

// ---------------- attention: one warp per point ----------------
__global__ __launch_bounds__(256) void attn_kernel(
    const float* __restrict__ fd1w, const float* __restrict__ fd1b)
{
    int warp = threadIdx.x >> 5, lane = threadIdx.x & 31;
    int p = blockIdx.x * 8 + warp;            // 16384 points
    int d0 = lane * 8;                        // lane owns dims d0..d0+7
    int b = p >> 12;

    const float* qrow = g_QKV + (size_t)p * 1024;
    float q[8], qp[8];
    *(float4*)(q)      = *(const float4*)(qrow + d0);
    *(float4*)(q + 4)  = *(const float4*)(qrow + d0 + 4);
    *(float4*)(qp)     = *(const float4*)(qrow + 768 + d0);
    *(float4*)(qp + 4) = *(const float4*)(qrow + 768 + d0 + 4);

    float f1x[8], f1y[8], f1z[8], hb0[8];
    *(float4*)(f1x)     = *(const float4*)(fd1w + 0 * 256 + d0);
    *(float4*)(f1x + 4) = *(const float4*)(fd1w + 0 * 256 + d0 + 4);
    *(float4*)(f1y)     = *(const float4*)(fd1w + 1 * 256 + d0);
    *(float4*)(f1y + 4) = *(const float4*)(fd1w + 1 * 256 + d0 + 4);
    *(float4*)(f1z)     = *(const float4*)(fd1w + 2 * 256 + d0);
    *(float4*)(f1z + 4) = *(const float4*)(fd1w + 2 * 256 + d0 + 4);
    *(float4*)(hb0)     = *(const float4*)(fd1b + d0);
    *(float4*)(hb0 + 4) = *(const float4*)(fd1b + d0 + 4);

    float4 me = g_pts[p];
    float px = me.x, py = me.y, pz = me.z;
    const int* kidx = g_knn + p * 16;
    const float*  batQKV = g_QKV + (size_t)(b << 12) * 1024;
    const float4* batpts = g_pts + (b << 12);

    // ---- pass 1: logits ----
    float mylogit = -1e30f;
    for (int k = 0; k < 16; k++) {
        int idx = __ldg(kidx + k);
        float4 nb = __ldg(batpts + idx);
        float dx = px - nb.x, dy = py - nb.y, dz = pz - nb.z;
        float h[8];
#pragma unroll
        for (int i = 0; i < 8; i++) {
            float t = fmaf(dx, f1x[i], hb0[i]);
            t = fmaf(dy, f1y[i], t);
            t = fmaf(dz, f1z[i], t);
            h[i] = fmaxf(t, 0.f);
        }
        const float* kf = batQKV + (size_t)idx * 1024 + 256 + d0;
        float kfv[8];
        *(float4*)(kfv)     = __ldg((const float4*)kf);
        *(float4*)(kfv + 4) = __ldg((const float4*)(kf + 4));
        float s = 0.f;
#pragma unroll
        for (int i = 0; i < 8; i++) {
            s = fmaf(q[i], kfv[i], s);
            s = fmaf(h[i], qp[i], s);    // q . pos  (via qp = fd2 @ q)
        }
#pragma unroll
        for (int o = 16; o >= 1; o >>= 1) s += __shfl_xor_sync(0xffffffffu, s, o);
        if (lane == k) mylogit = s * 0.0625f;   // / sqrt(256)
    }

    // ---- softmax over 16 logits ----
    float m = mylogit;
#pragma unroll
    for (int o = 16; o >= 1; o >>= 1) m = fmaxf(m, __shfl_xor_sync(0xffffffffu, m, o));
    float e = expf(mylogit - m);
    float ssum = e;
#pragma unroll
    for (int o = 16; o >= 1; o >>= 1) ssum += __shfl_xor_sync(0xffffffffu, ssum, o);
    float attn = e / ssum;

    // ---- pass 2: weighted sums ----
    float av[8], hbar[8];
#pragma unroll
    for (int i = 0; i < 8; i++) { av[i] = 0.f; hbar[i] = 0.f; }
    for (int k = 0; k < 16; k++) {
        float a = __shfl_sync(0xffffffffu, attn, k);
        int idx = __ldg(kidx + k);
        float4 nb = __ldg(batpts + idx);
        float dx = px - nb.x, dy = py - nb.y, dz = pz - nb.z;
        float h[8];
#pragma unroll
        for (int i = 0; i < 8; i++) {
            float t = fmaf(dx, f1x[i], hb0[i]);
            t = fmaf(dy, f1y[i], t);
            t = fmaf(dz, f1z[i], t);
            h[i] = fmaxf(t, 0.f);
        }
        const float* vf = batQKV + (size_t)idx * 1024 + 512 + d0;
        float vv[8];
        *(float4*)(vv)     = __ldg((const float4*)vf);
        *(float4*)(vv + 4) = __ldg((const float4*)(vf + 4));
#pragma unroll
        for (int i = 0; i < 8; i++) {
            av[i]   = fmaf(a, vv[i], av[i]);
            hbar[i] = fmaf(a, h[i], hbar[i]);
        }
    }
    float* hap = g_HA + (size_t)p * 512 + d0;
    *(float4*)(hap)           = *(float4*)(hbar);
    *(float4*)(hap + 4)       = *(float4*)(hbar + 4);
    *(float4*)(hap + 256)     = *(float4*)(av);
    *(float4*)(hap + 256 + 4) = *(float4*)(av + 4);
}

// ---------------- launch ----------------
extern "C" void kernel_launch(void* const* d_in, const int* in_sizes, int n_in,
                              void* d_out, int out_size)
{
    const float* features = (const float*)d_in[0];
    const float* xyz  = (const float*)d_in[1];
    const float* fc1w = (const float*)d_in[2];
    const float* fc1b = (const float*)d_in[3];
    const float* fc2w = (const float*)d_in[4];
    const float* fc2b = (const float*)d_in[5];
    const float* fd1w = (const float*)d_in[6];
    const float* fd1b = (const float*)d_in[7];
    const float* fd2w = (const float*)d_in[8];
    const float* fd2b = (const float*)d_in[9];
    const float* wq   = (const float*)d_in[10];
    const float* wk   = (const float*)d_in[11];
    const float* wv   = (const float*)d_in[12];
    float* out = (float*)d_out;

    prep_wc_k<<<(DPD * 768) / 256, 256>>>(fc1w, fc1b, wq, wk, wv);
    prep_qp_k<<<(DPD * 256) / 256, 256>>>(fd2w);
    prep_wo_k<<<(512 * DPD) / 256, 256>>>(fd2w, fd2b, fc2w, fc2b);
    pack_xyz_k<<<ROWS / 256, 256>>>(xyz);
    knn_kernel<<<ROWS / 8, 256>>>();   // warp per query

    // QKV|QP = features @ Wc + bc        [16384,1024]
    sgemm_k<0><<<dim3(8, 128), 256>>>(features, nullptr, nullptr, 1024, 128, 128);
    // attention -> HA = [HBAR | AV]       [16384,512]
    attn_kernel<<<ROWS / 8, 256>>>(fd1w, fd1b);
    // OUT = HA @ Wo + bo + features  -> transposed [4,128,4096]
    sgemm_k<1><<<dim3(1, 128), 256>>>(nullptr, features, out, 128, 512, 512);
}

// round 5
// speedup vs baseline: 1.6384x; 1.6384x over previous
#include <cuda_runtime.h>

#define BATCH 4
#define NPTS  4096
#define KNB   16
#define DPD   128
#define DMD   256
#define ROWS  (BATCH * NPTS)   // 16384

// ---------------- scratch (static device globals; no allocations) ----------------
__device__ float  g_Wc[DPD * 1024];          // [128,1024] = fc1@(wq | wk | wv | wq@fd2^T)
__device__ float  g_bc[1024];
__device__ float  g_Wo[512 * DPD];           // [512,128]  = [fd2@fc2 ; fc2]
__device__ float  g_bo[DPD];                 // fd2b@fc2 + fc2b
__device__ float4 g_pts[ROWS];               // (x,y,z, |xyz|^2)
__device__ int    g_knn[ROWS * KNB];
__device__ float  g_QKV[(size_t)ROWS * 1024];// [16384,1024] (q|k|v|qp)
__device__ float  g_HA[(size_t)ROWS * 512];  // [16384,512]  (hbar|av)

// ---------------- prep kernels ----------------
__global__ __launch_bounds__(256) void prep_wc_k(
    const float* __restrict__ fc1w, const float* __restrict__ fc1b,
    const float* __restrict__ wq,   const float* __restrict__ wk,
    const float* __restrict__ wv)
{
    int t = blockIdx.x * 256 + threadIdx.x;   // 0 .. 128*768-1
    int r = t / 768, c = t % 768;
    const float* w = (c < 256) ? wq : (c < 512) ? wk : wv;
    int cc = c & 255;
    float s = 0.f;
#pragma unroll 4
    for (int m = 0; m < 256; m++)
        s = fmaf(__ldg(fc1w + r * 256 + m), __ldg(w + m * 256 + cc), s);
    g_Wc[r * 1024 + c] = s;
    if (r == 0) {
        float b = 0.f;
#pragma unroll 4
        for (int m = 0; m < 256; m++)
            b = fmaf(__ldg(fc1b + m), __ldg(w + m * 256 + cc), b);
        g_bc[c] = b;
    }
}

// qp block: Wc[:,768+d] = sum_m Wc_q[:,m] * fd2w[d,m]
__global__ __launch_bounds__(256) void prep_qp_k(const float* __restrict__ fd2w)
{
    int t = blockIdx.x * 256 + threadIdx.x;   // 0 .. 128*256-1
    int r = t >> 8, d = t & 255;
    float s = 0.f;
#pragma unroll 4
    for (int m = 0; m < 256; m++)
        s = fmaf(g_Wc[r * 1024 + m], __ldg(fd2w + d * 256 + m), s);
    g_Wc[r * 1024 + 768 + d] = s;
    if (r == 0) {
        float b = 0.f;
#pragma unroll 4
        for (int m = 0; m < 256; m++)
            b = fmaf(g_bc[m], __ldg(fd2w + d * 256 + m), b);
        g_bc[768 + d] = b;
    }
}

// Wo = [fd2w@fc2w ; fc2w]  [512,128],  bo = fd2b@fc2w + fc2b
__global__ __launch_bounds__(256) void prep_wo_k(
    const float* __restrict__ fd2w, const float* __restrict__ fd2b,
    const float* __restrict__ fc2w, const float* __restrict__ fc2b)
{
    int t = blockIdx.x * 256 + threadIdx.x;   // 0 .. 512*128-1
    int j = t >> 7, c = t & 127;
    float s;
    if (j < 256) {
        s = 0.f;
#pragma unroll 4
        for (int m = 0; m < 256; m++)
            s = fmaf(__ldg(fd2w + j * 256 + m), __ldg(fc2w + m * 128 + c), s);
    } else {
        s = __ldg(fc2w + (j - 256) * 128 + c);
    }
    g_Wo[j * 128 + c] = s;
    if (j == 0) {
        float b = 0.f;
#pragma unroll 4
        for (int m = 0; m < 256; m++)
            b = fmaf(__ldg(fd2b + m), __ldg(fc2w + m * 128 + c), b);
        g_bo[c] = b + __ldg(fc2b + c);
    }
}

__global__ void pack_xyz_k(const float* __restrict__ xyz)
{
    int p = blockIdx.x * 256 + threadIdx.x;   // 16384
    float x = xyz[p * 3], y = xyz[p * 3 + 1], z = xyz[p * 3 + 2];
    float sq = x * x; sq = fmaf(y, y, sq); sq = fmaf(z, z, sq);
    g_pts[p] = make_float4(x, y, z, sq);
}

// ---------------- KNN: warp per query, distributed sorted top-16 ----------------
__global__ __launch_bounds__(256) void knn_kernel()
{
    int p    = (blockIdx.x * 256 + threadIdx.x) >> 5;
    int lane = threadIdx.x & 31;
    int b = p >> 12;
    const float4* bp = g_pts + (b << 12);
    float4 me = __ldg(bp + (p & 4095));
    float qx = me.x, qy = me.y, qz = me.z, qsq = me.w;

    float ld = 3.0e38f;
    int   li = 0;
    float worst = 3.0e38f;

    for (int j0 = 0; j0 < 4096; j0 += 32) {
        float4 o = __ldg(bp + j0 + lane);
        float tt = qx * o.x; tt = fmaf(qy, o.y, tt); tt = fmaf(qz, o.z, tt);
        float d2 = fmaf(-2.f, tt, qsq + o.w);   // exact reference formula
        unsigned ball = __ballot_sync(0xffffffffu, d2 < worst);
        while (ball) {
            int src = __ffs(ball) - 1;
            ball &= ball - 1;
            float v = __shfl_sync(0xffffffffu, d2, src);
            if (v < worst) {
                int vi = j0 + src;
                float pd = __shfl_up_sync(0xffffffffu, ld, 1);
                int   pi = __shfl_up_sync(0xffffffffu, li, 1);
                bool pgt = (lane != 0) && (pd > v);
                if (ld > v) {
                    if (pgt) { ld = pd; li = pi; }
                    else     { ld = v;  li = vi; }
                }
                worst = __shfl_sync(0xffffffffu, ld, 15);
            }
        }
    }
    if (lane < 16) g_knn[p * 16 + lane] = li;
}

// ---------------- SGEMM: 128x128 tile, 8x8 microtile, BK=8, double-buffered ----------------
// MODE 0: QKV = features @ g_Wc + g_bc             [16384,1024], K=128, lda=128
// MODE 1: OUT = g_HA @ g_Wo + g_bo + features      [16384,128],  K=512, lda=512
//         (stored transposed [B,DP,N])
template<int MODE>
__global__ __launch_bounds__(256) void sgemm_k(
    const float* __restrict__ Aext, const float* __restrict__ addExt,
    float* __restrict__ Cext, int N, int Kd, int lda)
{
    const float* A = (MODE == 0) ? Aext : g_HA;
    const float* B = (MODE == 0) ? g_Wc : g_Wo;
    const float* bias = (MODE == 0) ? g_bc : g_bo;
    float* C = (MODE == 0) ? g_QKV : Cext;

    __shared__ float As[2][8][128];
    __shared__ float Bs[2][8][128];
    int tid  = threadIdx.x;
    int brow = blockIdx.y * 128;
    int bcol = blockIdx.x * 128;
    int ar = tid >> 1, ac = (tid & 1) * 4;
    int br = tid >> 5, bc = (tid & 31) * 4;
    int ty = tid >> 4, tx = tid & 15;

    float acc[8][8];
#pragma unroll
    for (int i = 0; i < 8; i++)
#pragma unroll
        for (int j = 0; j < 8; j++) acc[i][j] = 0.f;

    const float* Aptr = A + (size_t)(brow + ar) * lda + ac;
    const float* Bptr = B + (size_t)br * N + bcol + bc;

    // prologue: tile 0 -> buffer 0
    float4 av = *(const float4*)(Aptr);
    float4 bv = *(const float4*)(Bptr);
    As[0][ac + 0][ar] = av.x; As[0][ac + 1][ar] = av.y;
    As[0][ac + 2][ar] = av.z; As[0][ac + 3][ar] = av.w;
    *(float4*)(&Bs[0][br][bc]) = bv;
    __syncthreads();

    int rbuf = 0;
    for (int k0 = 8; k0 < Kd; k0 += 8) {
        // prefetch next tile from gmem (overlaps with compute below)
        av = *(const float4*)(Aptr + k0);
        bv = *(const float4*)(Bptr + (size_t)k0 * N);
#pragma unroll
        for (int kk = 0; kk < 8; kk++) {
            float a8[8], b8[8];
            *(float4*)(a8)     = *(const float4*)(&As[rbuf][kk][ty * 8]);
            *(float4*)(a8 + 4) = *(const float4*)(&As[rbuf][kk][ty * 8 + 4]);
            *(float4*)(b8)     = *(const float4*)(&Bs[rbuf][kk][tx * 8]);
            *(float4*)(b8 + 4) = *(const float4*)(&Bs[rbuf][kk][tx * 8 + 4]);
#pragma unroll
            for (int i = 0; i < 8; i++)
#pragma unroll
                for (int j = 0; j < 8; j++)
                    acc[i][j] = fmaf(a8[i], b8[j], acc[i][j]);
        }
        int wbuf = rbuf ^ 1;
        As[wbuf][ac + 0][ar] = av.x; As[wbuf][ac + 1][ar] = av.y;
        As[wbuf][ac + 2][ar] = av.z; As[wbuf][ac + 3][ar] = av.w;
        *(float4*)(&Bs[wbuf][br][bc]) = bv;
        __syncthreads();
        rbuf = wbuf;
    }
    // epilogue tile
#pragma unroll
    for (int kk = 0; kk < 8; kk++) {
        float a8[8], b8[8];
        *(float4*)(a8)     = *(const float4*)(&As[rbuf][kk][ty * 8]);
        *(float4*)(a8 + 4) = *(const float4*)(&As[rbuf][kk][ty * 8 + 4]);
        *(float4*)(b8)     = *(const float4*)(&Bs[rbuf][kk][tx * 8]);
        *(float4*)(b8 + 4) = *(const float4*)(&Bs[rbuf][kk][tx * 8 + 4]);
#pragma unroll
        for (int i = 0; i < 8; i++)
#pragma unroll
            for (int j = 0; j < 8; j++)
                acc[i][j] = fmaf(a8[i], b8[j], acc[i][j]);
    }

    float bb[8];
#pragma unroll
    for (int j = 0; j < 8; j++) bb[j] = bias[bcol + tx * 8 + j];

#pragma unroll
    for (int i = 0; i < 8; i++) {
        int r = brow + ty * 8 + i;
#pragma unroll
        for (int j = 0; j < 8; j++) {
            int c = bcol + tx * 8 + j;
            float v = acc[i][j] + bb[j];
            if (MODE == 1) {
                v += addExt[(size_t)r * DPD + c];   // + features residual
                C[(size_t)((r >> 12) * DPD + c) * NPTS + (r & 4095)] = v;  // [B,DP,N]
            } else {
                C[(size_t)r * 1024 + c] = v;
            }
        }
    }
}

// ---------------- attention: one warp per point ----------------
__global__ __launch_bounds__(256) void attn_kernel(
    const float* __restrict__ fd1w, const float* __restrict__ fd1b)
{
    int warp = threadIdx.x >> 5, lane = threadIdx.x & 31;
    int p = blockIdx.x * 8 + warp;            // 16384 points
    int d0 = lane * 8;                        // lane owns dims d0..d0+7
    int b = p >> 12;

    const float* qrow = g_QKV + (size_t)p * 1024;
    float q[8], qp[8];
    *(float4*)(q)      = *(const float4*)(qrow + d0);
    *(float4*)(q + 4)  = *(const float4*)(qrow + d0 + 4);
    *(float4*)(qp)     = *(const float4*)(qrow + 768 + d0);
    *(float4*)(qp + 4) = *(const float4*)(qrow + 768 + d0 + 4);

    float f1x[8], f1y[8], f1z[8], hb0[8];
    *(float4*)(f1x)     = *(const float4*)(fd1w + 0 * 256 + d0);
    *(float4*)(f1x + 4) = *(const float4*)(fd1w + 0 * 256 + d0 + 4);
    *(float4*)(f1y)     = *(const float4*)(fd1w + 1 * 256 + d0);
    *(float4*)(f1y + 4) = *(const float4*)(fd1w + 1 * 256 + d0 + 4);
    *(float4*)(f1z)     = *(const float4*)(fd1w + 2 * 256 + d0);
    *(float4*)(f1z + 4) = *(const float4*)(fd1w + 2 * 256 + d0 + 4);
    *(float4*)(hb0)     = *(const float4*)(fd1b + d0);
    *(float4*)(hb0 + 4) = *(const float4*)(fd1b + d0 + 4);

    float4 me = g_pts[p];
    float px = me.x, py = me.y, pz = me.z;
    const int* kidx = g_knn + p * 16;
    const float*  batQKV = g_QKV + (size_t)(b << 12) * 1024;
    const float4* batpts = g_pts + (b << 12);

    // ---- pass 1: logits ----
    float mylogit = -1e30f;
    for (int k = 0; k < 16; k++) {
        int idx = __ldg(kidx + k);
        float4 nb = __ldg(batpts + idx);
        float dx = px - nb.x, dy = py - nb.y, dz = pz - nb.z;
        float h[8];
#pragma unroll
        for (int i = 0; i < 8; i++) {
            float t = fmaf(dx, f1x[i], hb0[i]);
            t = fmaf(dy, f1y[i], t);
            t = fmaf(dz, f1z[i], t);
            h[i] = fmaxf(t, 0.f);
        }
        const float* kf = batQKV + (size_t)idx * 1024 + 256 + d0;
        float kfv[8];
        *(float4*)(kfv)     = __ldg((const float4*)kf);
        *(float4*)(kfv + 4) = __ldg((const float4*)(kf + 4));
        float s = 0.f;
#pragma unroll
        for (int i = 0; i < 8; i++) {
            s = fmaf(q[i], kfv[i], s);
            s = fmaf(h[i], qp[i], s);    // q . pos  (via qp = fd2 @ q)
        }
#pragma unroll
        for (int o = 16; o >= 1; o >>= 1) s += __shfl_xor_sync(0xffffffffu, s, o);
        if (lane == k) mylogit = s * 0.0625f;   // / sqrt(256)
    }

    // ---- softmax over 16 logits ----
    float m = mylogit;
#pragma unroll
    for (int o = 16; o >= 1; o >>= 1) m = fmaxf(m, __shfl_xor_sync(0xffffffffu, m, o));
    float e = expf(mylogit - m);
    float ssum = e;
#pragma unroll
    for (int o = 16; o >= 1; o >>= 1) ssum += __shfl_xor_sync(0xffffffffu, ssum, o);
    float attn = e / ssum;

    // ---- pass 2: weighted sums ----
    float av[8], hbar[8];
#pragma unroll
    for (int i = 0; i < 8; i++) { av[i] = 0.f; hbar[i] = 0.f; }
    for (int k = 0; k < 16; k++) {
        float a = __shfl_sync(0xffffffffu, attn, k);
        int idx = __ldg(kidx + k);
        float4 nb = __ldg(batpts + idx);
        float dx = px - nb.x, dy = py - nb.y, dz = pz - nb.z;
        float h[8];
#pragma unroll
        for (int i = 0; i < 8; i++) {
            float t = fmaf(dx, f1x[i], hb0[i]);
            t = fmaf(dy, f1y[i], t);
            t = fmaf(dz, f1z[i], t);
            h[i] = fmaxf(t, 0.f);
        }
        const float* vf = batQKV + (size_t)idx * 1024 + 512 + d0;
        float vv[8];
        *(float4*)(vv)     = __ldg((const float4*)vf);
        *(float4*)(vv + 4) = __ldg((const float4*)(vf + 4));
#pragma unroll
        for (int i = 0; i < 8; i++) {
            av[i]   = fmaf(a, vv[i], av[i]);
            hbar[i] = fmaf(a, h[i], hbar[i]);
        }
    }
    float* hap = g_HA + (size_t)p * 512 + d0;
    *(float4*)(hap)           = *(float4*)(hbar);
    *(float4*)(hap + 4)       = *(float4*)(hbar + 4);
    *(float4*)(hap + 256)     = *(float4*)(av);
    *(float4*)(hap + 256 + 4) = *(float4*)(av + 4);
}

// ---------------- launch ----------------
extern "C" void kernel_launch(void* const* d_in, const int* in_sizes, int n_in,
                              void* d_out, int out_size)
{
    const float* features = (const float*)d_in[0];
    const float* xyz  = (const float*)d_in[1];
    const float* fc1w = (const float*)d_in[2];
    const float* fc1b = (const float*)d_in[3];
    const float* fc2w = (const float*)d_in[4];
    const float* fc2b = (const float*)d_in[5];
    const float* fd1w = (const float*)d_in[6];
    const float* fd1b = (const float*)d_in[7];
    const float* fd2w = (const float*)d_in[8];
    const float* fd2b = (const float*)d_in[9];
    const float* wq   = (const float*)d_in[10];
    const float* wk   = (const float*)d_in[11];
    const float* wv   = (const float*)d_in[12];
    float* out = (float*)d_out;

    prep_wc_k<<<(DPD * 768) / 256, 256>>>(fc1w, fc1b, wq, wk, wv);
    prep_qp_k<<<(DPD * 256) / 256, 256>>>(fd2w);
    prep_wo_k<<<(512 * DPD) / 256, 256>>>(fd2w, fd2b, fc2w, fc2b);
    pack_xyz_k<<<ROWS / 256, 256>>>(xyz);
    knn_kernel<<<ROWS / 8, 256>>>();   // warp per query

    // QKV|QP = features @ Wc + bc        [16384,1024]
    sgemm_k<0><<<dim3(8, 128), 256>>>(features, nullptr, nullptr, 1024, 128, 128);
    // attention -> HA = [HBAR | AV]       [16384,512]
    attn_kernel<<<ROWS / 8, 256>>>(fd1w, fd1b);
    // OUT = HA @ Wo + bo + features  -> transposed [4,128,4096]
    sgemm_k<1><<<dim3(1, 128), 256>>>(nullptr, features, out, 128, 512, 512);
}

// round 7
// speedup vs baseline: 1.9208x; 1.1723x over previous
#include <cuda_runtime.h>
#include <cuda_bf16.h>
#include <cstdint>

#define BATCH 4
#define NPTS  4096
#define KNB   16
#define DPD   128
#define DMD   256
#define ROWS  (BATCH * NPTS)   // 16384

// ---------------- scratch (static device globals; no allocations) ----------------
__device__ float  g_Wc[DPD * 1024];           // [128,1024] = fc1@(wq | wk | wv | wq@fd2^T)
__device__ float  g_bc[1024];
__device__ float  g_Wo[512 * DPD];            // [512,128]  = [fd2@fc2 ; fc2]
__device__ float  g_bo[DPD];
__device__ float4 g_pts[ROWS];
__device__ int    g_knn[ROWS * KNB];
__device__ float  g_QKV[(size_t)ROWS * 1024]; // [16384,1024] (q|k|v|qp) fp32
// split-bf16 GEMM operands: A' = [Ah|Ah|Al], B' = [Bh|Bl|Bh] along K
__device__ __nv_bfloat16 g_Abf0[(size_t)ROWS * 384];   // features split, K'=384
__device__ __nv_bfloat16 g_Bbf0[1024 * 384];           // Wc^T split
__device__ __nv_bfloat16 g_Abf1[(size_t)ROWS * 1536];  // [HBAR|AV] split, K'=1536
__device__ __nv_bfloat16 g_Bbf1[128 * 1536];           // Wo^T split

// ---------------- warp-MMA helpers (base-ISA: sm_80+, valid on sm_103) ----------------
__device__ __forceinline__ uint32_t smem_u32(const void* p) {
    uint32_t a;
    asm("{ .reg .u64 t; cvta.to.shared.u64 t, %1; cvt.u32.u64 %0, t; }" : "=r"(a) : "l"(p));
    return a;
}
__device__ __forceinline__ void ldsm4(uint32_t& r0, uint32_t& r1, uint32_t& r2, uint32_t& r3,
                                      uint32_t addr) {
    asm volatile("ldmatrix.sync.aligned.m8n8.x4.shared.b16 {%0,%1,%2,%3}, [%4];"
                 : "=r"(r0), "=r"(r1), "=r"(r2), "=r"(r3) : "r"(addr));
}
__device__ __forceinline__ void mma16816(float* d, const uint32_t* a, uint32_t b0, uint32_t b1) {
    asm volatile("mma.sync.aligned.m16n8k16.row.col.f32.bf16.bf16.f32 "
                 "{%0,%1,%2,%3}, {%4,%5,%6,%7}, {%8,%9}, {%0,%1,%2,%3};"
                 : "+f"(d[0]), "+f"(d[1]), "+f"(d[2]), "+f"(d[3])
                 : "r"(a[0]), "r"(a[1]), "r"(a[2]), "r"(a[3]), "r"(b0), "r"(b1));
}

// ---------------- prep kernels ----------------
__global__ __launch_bounds__(256) void prep_wc_k(
    const float* __restrict__ fc1w, const float* __restrict__ fc1b,
    const float* __restrict__ wq,   const float* __restrict__ wk,
    const float* __restrict__ wv)
{
    int t = blockIdx.x * 256 + threadIdx.x;   // 0 .. 128*768-1
    int r = t / 768, c = t % 768;
    const float* w = (c < 256) ? wq : (c < 512) ? wk : wv;
    int cc = c & 255;
    float s = 0.f;
#pragma unroll 4
    for (int m = 0; m < 256; m++)
        s = fmaf(__ldg(fc1w + r * 256 + m), __ldg(w + m * 256 + cc), s);
    g_Wc[r * 1024 + c] = s;
    if (r == 0) {
        float b = 0.f;
#pragma unroll 4
        for (int m = 0; m < 256; m++)
            b = fmaf(__ldg(fc1b + m), __ldg(w + m * 256 + cc), b);
        g_bc[c] = b;
    }
}

__global__ __launch_bounds__(256) void prep_qp_k(const float* __restrict__ fd2w)
{
    int t = blockIdx.x * 256 + threadIdx.x;   // 0 .. 128*256-1
    int r = t >> 8, d = t & 255;
    float s = 0.f;
#pragma unroll 4
    for (int m = 0; m < 256; m++)
        s = fmaf(g_Wc[r * 1024 + m], __ldg(fd2w + d * 256 + m), s);
    g_Wc[r * 1024 + 768 + d] = s;
    if (r == 0) {
        float b = 0.f;
#pragma unroll 4
        for (int m = 0; m < 256; m++)
            b = fmaf(g_bc[m], __ldg(fd2w + d * 256 + m), b);
        g_bc[768 + d] = b;
    }
}

__global__ __launch_bounds__(256) void prep_wo_k(
    const float* __restrict__ fd2w, const float* __restrict__ fd2b,
    const float* __restrict__ fc2w, const float* __restrict__ fc2b)
{
    int t = blockIdx.x * 256 + threadIdx.x;   // 0 .. 512*128-1
    int j = t >> 7, c = t & 127;
    float s;
    if (j < 256) {
        s = 0.f;
#pragma unroll 4
        for (int m = 0; m < 256; m++)
            s = fmaf(__ldg(fd2w + j * 256 + m), __ldg(fc2w + m * 128 + c), s);
    } else {
        s = __ldg(fc2w + (j - 256) * 128 + c);
    }
    g_Wo[j * 128 + c] = s;
    if (j == 0) {
        float b = 0.f;
#pragma unroll 4
        for (int m = 0; m < 256; m++)
            b = fmaf(__ldg(fd2b + m), __ldg(fc2w + m * 128 + c), b);
        g_bo[c] = b + __ldg(fc2b + c);
    }
}

__global__ void pack_xyz_k(const float* __restrict__ xyz)
{
    int p = blockIdx.x * 256 + threadIdx.x;   // 16384
    float x = xyz[p * 3], y = xyz[p * 3 + 1], z = xyz[p * 3 + 2];
    float sq = x * x; sq = fmaf(y, y, sq); sq = fmaf(z, z, sq);
    g_pts[p] = make_float4(x, y, z, sq);
}

// ---------------- bf16 split converts ----------------
__device__ __forceinline__ void split2(float x0, float x1, __nv_bfloat162& hi, __nv_bfloat162& lo)
{
    __nv_bfloat16 h0 = __float2bfloat16(x0);
    __nv_bfloat16 h1 = __float2bfloat16(x1);
    hi.x = h0; hi.y = h1;
    lo.x = __float2bfloat16(x0 - __bfloat162float(h0));
    lo.y = __float2bfloat16(x1 - __bfloat162float(h1));
}

__global__ __launch_bounds__(256) void conv_feat_k(const float* __restrict__ f)
{
    int t = blockIdx.x * 256 + threadIdx.x;   // 16384*64
    int r = t >> 6, c2 = (t & 63) << 1;
    __nv_bfloat162 hi, lo;
    split2(f[r * 128 + c2], f[r * 128 + c2 + 1], hi, lo);
    __nv_bfloat162* dst = (__nv_bfloat162*)g_Abf0 + (size_t)r * 192;
    int i = c2 >> 1;
    dst[i] = hi; dst[i + 64] = hi; dst[i + 128] = lo;   // A' = [Ah|Ah|Al]
}

__global__ __launch_bounds__(256) void conv_b0_k()
{
    int t = blockIdx.x * 256 + threadIdx.x;   // 1024*64
    int n = t >> 6, k2 = (t & 63) << 1;
    __nv_bfloat162 hi, lo;
    split2(g_Wc[k2 * 1024 + n], g_Wc[(k2 + 1) * 1024 + n], hi, lo);
    __nv_bfloat162* dst = (__nv_bfloat162*)g_Bbf0 + (size_t)n * 192;
    int i = k2 >> 1;
    dst[i] = hi; dst[i + 64] = lo; dst[i + 128] = hi;   // B' = [Bh|Bl|Bh]
}

__global__ __launch_bounds__(256) void conv_b1_k()
{
    int t = blockIdx.x * 256 + threadIdx.x;   // 128*256
    int n = t >> 8, k2 = (t & 255) << 1;
    __nv_bfloat162 hi, lo;
    split2(g_Wo[k2 * 128 + n], g_Wo[(k2 + 1) * 128 + n], hi, lo);
    __nv_bfloat162* dst = (__nv_bfloat162*)g_Bbf1 + (size_t)n * 768;
    int i = k2 >> 1;
    dst[i] = hi; dst[i + 256] = lo; dst[i + 512] = hi;
}

// ---------------- KNN: warp per query, distributed sorted top-16 ----------------
__global__ __launch_bounds__(256) void knn_kernel()
{
    int p    = (blockIdx.x * 256 + threadIdx.x) >> 5;
    int lane = threadIdx.x & 31;
    int b = p >> 12;
    const float4* bp = g_pts + (b << 12);
    float4 me = __ldg(bp + (p & 4095));
    float qx = me.x, qy = me.y, qz = me.z, qsq = me.w;

    float ld = 3.0e38f;
    int   li = 0;
    float worst = 3.0e38f;

    for (int j0 = 0; j0 < 4096; j0 += 32) {
        float4 o = __ldg(bp + j0 + lane);
        float tt = qx * o.x; tt = fmaf(qy, o.y, tt); tt = fmaf(qz, o.z, tt);
        float d2 = fmaf(-2.f, tt, qsq + o.w);
        unsigned ball = __ballot_sync(0xffffffffu, d2 < worst);
        while (ball) {
            int src = __ffs(ball) - 1;
            ball &= ball - 1;
            float v = __shfl_sync(0xffffffffu, d2, src);
            if (v < worst) {
                int vi = j0 + src;
                float pd = __shfl_up_sync(0xffffffffu, ld, 1);
                int   pi = __shfl_up_sync(0xffffffffu, li, 1);
                bool pgt = (lane != 0) && (pd > v);
                if (ld > v) {
                    if (pgt) { ld = pd; li = pi; }
                    else     { ld = v;  li = vi; }
                }
                worst = __shfl_sync(0xffffffffu, ld, 15);
            }
        }
    }
    if (lane < 16) g_knn[p * 16 + lane] = li;
}

// ---------------- bf16 mma.sync GEMM: 128x128 block, BK=64, 8 warps ----------------
// MODE 0: g_QKV = Abf0 @ Bbf0^T + bc              M=16384, N=1024, K'=384
// MODE 1: out   = Abf1 @ Bbf1^T + bo + features   (transposed store), N=128, K'=1536
template<int MODE>
__global__ __launch_bounds__(256) void mma_gemm_k(const float* __restrict__ feat,
                                                  float* __restrict__ outp)
{
    constexpr int KP  = (MODE == 0) ? 384 : 1536;
    constexpr int NCH = KP / 64;
    const __nv_bfloat16* A  = (MODE == 0) ? g_Abf0 : g_Abf1;
    const __nv_bfloat16* Bm = (MODE == 0) ? g_Bbf0 : g_Bbf1;
    const float* bias = (MODE == 0) ? g_bc : g_bo;

    __shared__ __align__(128) char smbuf[32768];   // A tile 16KB | B tile 16KB
    __nv_bfloat16* As = (__nv_bfloat16*)smbuf;
    __nv_bfloat16* Bs = (__nv_bfloat16*)(smbuf + 16384);

    int tid = threadIdx.x, lane = tid & 31, wid = tid >> 5;
    int brow = blockIdx.y * 128, bcol = blockIdx.x * 128;
    int wm = wid & 1, wn = wid >> 1;               // warp tile 64x32 at (wm*64, wn*32)

    // ---- global->smem mapping: row = tid/2, four 16B blocks per thread ----
    int gr   = tid >> 1;
    int gkb0 = (tid & 1) * 4;
    const uint4* agp = (const uint4*)(A  + (size_t)(brow + gr) * KP) + gkb0;
    const uint4* bgp = (const uint4*)(Bm + (size_t)(bcol + gr) * KP) + gkb0;
    uint32_t soff[4];
#pragma unroll
    for (int i = 0; i < 4; i++)
        soff[i] = gr * 128 + (((gkb0 + i) ^ (gr & 7)) << 4);

    // ---- ldmatrix per-thread bases ----
    uint32_t sAu = smem_u32(As), sBu = smem_u32(Bs);
    uint32_t abase[4]; int axr[4];
#pragma unroll
    for (int mt = 0; mt < 4; mt++) {
        int ra = wm * 64 + mt * 16 + (lane & 15);
        abase[mt] = sAu + ra * 128; axr[mt] = ra & 7;
    }
    int khalf_a = lane >> 4;
    uint32_t bbase[2]; int bxr[2];
#pragma unroll
    for (int nt = 0; nt < 2; nt++) {
        int rb = wn * 32 + nt * 16 + ((lane >> 4) << 3) + (lane & 7);
        bbase[nt] = sBu + rb * 128; bxr[nt] = rb & 7;
    }
    int khalf_b = (lane >> 3) & 1;

    float acc[4][4][4];
#pragma unroll
    for (int mt = 0; mt < 4; mt++)
#pragma unroll
        for (int j = 0; j < 4; j++)
#pragma unroll
            for (int e = 0; e < 4; e++) acc[mt][j][e] = 0.f;

    uint4 va[4], vb[4];
#pragma unroll
    for (int i = 0; i < 4; i++) { va[i] = __ldg(agp + i); vb[i] = __ldg(bgp + i); }

    for (int c = 0; c < NCH; c++) {
#pragma unroll
        for (int i = 0; i < 4; i++) {
            *(uint4*)(smbuf + soff[i])         = va[i];
            *(uint4*)(smbuf + 16384 + soff[i]) = vb[i];
        }
        __syncthreads();
        if (c + 1 < NCH) {
#pragma unroll
            for (int i = 0; i < 4; i++) {
                va[i] = __ldg(agp + (c + 1) * 8 + i);
                vb[i] = __ldg(bgp + (c + 1) * 8 + i);
            }
        }
#pragma unroll
        for (int kk = 0; kk < 4; kk++) {
            uint32_t af[4][4], bf[2][4];
#pragma unroll
            for (int mt = 0; mt < 4; mt++)
                ldsm4(af[mt][0], af[mt][1], af[mt][2], af[mt][3],
                      abase[mt] + (((kk * 2 + khalf_a) ^ axr[mt]) << 4));
#pragma unroll
            for (int nt = 0; nt < 2; nt++)
                ldsm4(bf[nt][0], bf[nt][1], bf[nt][2], bf[nt][3],
                      bbase[nt] + (((kk * 2 + khalf_b) ^ bxr[nt]) << 4));
#pragma unroll
            for (int mt = 0; mt < 4; mt++)
#pragma unroll
                for (int j = 0; j < 4; j++)
                    mma16816(acc[mt][j], af[mt],
                             bf[j >> 1][(j & 1) * 2], bf[j >> 1][(j & 1) * 2 + 1]);
        }
        __syncthreads();
    }

    // ---- epilogue ----
    if (MODE == 0) {
#pragma unroll
        for (int mt = 0; mt < 4; mt++) {
            int r0 = brow + wm * 64 + mt * 16 + (lane >> 2);
#pragma unroll
            for (int j = 0; j < 4; j++) {
                int cc = bcol + wn * 32 + j * 8 + (lane & 3) * 2;
                float b0 = bias[cc], b1 = bias[cc + 1];
                float2 v0 = make_float2(acc[mt][j][0] + b0, acc[mt][j][1] + b1);
                float2 v1 = make_float2(acc[mt][j][2] + b0, acc[mt][j][3] + b1);
                *(float2*)(g_QKV + (size_t)r0 * 1024 + cc)       = v0;
                *(float2*)(g_QKV + (size_t)(r0 + 8) * 1024 + cc) = v1;
            }
        }
    } else {
        // stage 32-col chunks in padded smem, then coalesced transposed store
        float (*cs)[33] = (float(*)[33])smbuf;   // 128 x 33 f32 = 16896 B
        int bb = brow >> 12, n0 = brow & 4095;
        for (int q = 0; q < 4; q++) {
            __syncthreads();
            if (wn == q) {
#pragma unroll
                for (int mt = 0; mt < 4; mt++) {
                    int rl = wm * 64 + mt * 16 + (lane >> 2);
#pragma unroll
                    for (int j = 0; j < 4; j++) {
                        int cl = j * 8 + (lane & 3) * 2;       // local col in chunk
                        int gc = q * 32 + cl;                  // global output channel
                        float b0 = bias[gc], b1 = bias[gc + 1];
                        cs[rl][cl]     = acc[mt][j][0] + b0 + feat[(size_t)(brow + rl) * DPD + gc];
                        cs[rl][cl + 1] = acc[mt][j][1] + b1 + feat[(size_t)(brow + rl) * DPD + gc + 1];
                        cs[rl + 8][cl]     = acc[mt][j][2] + b0 + feat[(size_t)(brow + rl + 8) * DPD + gc];
                        cs[rl + 8][cl + 1] = acc[mt][j][3] + b1 + feat[(size_t)(brow + rl + 8) * DPD + gc + 1];
                    }
                }
            }
            __syncthreads();
            int rr = tid & 127, ch = tid >> 7;
#pragma unroll
            for (int c2 = 0; c2 < 32; c2 += 2) {
                int cc = c2 + ch;
                outp[(size_t)(bb * DPD + q * 32 + cc) * NPTS + n0 + rr] = cs[rr][cc];
            }
        }
    }
}

// ---------------- attention: one warp per point; writes split-bf16 [HBAR|AV] ----------------
__global__ __launch_bounds__(256) void attn_kernel(
    const float* __restrict__ fd1w, const float* __restrict__ fd1b)
{
    int warp = threadIdx.x >> 5, lane = threadIdx.x & 31;
    int p = blockIdx.x * 8 + warp;
    int d0 = lane * 8;
    int b = p >> 12;

    const float* qrow = g_QKV + (size_t)p * 1024;
    float q[8], qp[8];
    *(float4*)(q)      = *(const float4*)(qrow + d0);
    *(float4*)(q + 4)  = *(const float4*)(qrow + d0 + 4);
    *(float4*)(qp)     = *(const float4*)(qrow + 768 + d0);
    *(float4*)(qp + 4) = *(const float4*)(qrow + 768 + d0 + 4);

    float f1x[8], f1y[8], f1z[8], hb0[8];
    *(float4*)(f1x)     = *(const float4*)(fd1w + 0 * 256 + d0);
    *(float4*)(f1x + 4) = *(const float4*)(fd1w + 0 * 256 + d0 + 4);
    *(float4*)(f1y)     = *(const float4*)(fd1w + 1 * 256 + d0);
    *(float4*)(f1y + 4) = *(const float4*)(fd1w + 1 * 256 + d0 + 4);
    *(float4*)(f1z)     = *(const float4*)(fd1w + 2 * 256 + d0);
    *(float4*)(f1z + 4) = *(const float4*)(fd1w + 2 * 256 + d0 + 4);
    *(float4*)(hb0)     = *(const float4*)(fd1b + d0);
    *(float4*)(hb0 + 4) = *(const float4*)(fd1b + d0 + 4);

    float4 me = g_pts[p];
    float px = me.x, py = me.y, pz = me.z;
    const int* kidx = g_knn + p * 16;
    const float*  batQKV = g_QKV + (size_t)(b << 12) * 1024;
    const float4* batpts = g_pts + (b << 12);

    // ---- pass 1: logits ----
    float mylogit = -1e30f;
    for (int k = 0; k < 16; k++) {
        int idx = __ldg(kidx + k);
        float4 nb = __ldg(batpts + idx);
        float dx = px - nb.x, dy = py - nb.y, dz = pz - nb.z;
        float h[8];
#pragma unroll
        for (int i = 0; i < 8; i++) {
            float t = fmaf(dx, f1x[i], hb0[i]);
            t = fmaf(dy, f1y[i], t);
            t = fmaf(dz, f1z[i], t);
            h[i] = fmaxf(t, 0.f);
        }
        const float* kf = batQKV + (size_t)idx * 1024 + 256 + d0;
        float kfv[8];
        *(float4*)(kfv)     = __ldg((const float4*)kf);
        *(float4*)(kfv + 4) = __ldg((const float4*)(kf + 4));
        float s = 0.f;
#pragma unroll
        for (int i = 0; i < 8; i++) {
            s = fmaf(q[i], kfv[i], s);
            s = fmaf(h[i], qp[i], s);
        }
#pragma unroll
        for (int o = 16; o >= 1; o >>= 1) s += __shfl_xor_sync(0xffffffffu, s, o);
        if (lane == k) mylogit = s * 0.0625f;
    }

    // ---- softmax over 16 logits ----
    float m = mylogit;
#pragma unroll
    for (int o = 16; o >= 1; o >>= 1) m = fmaxf(m, __shfl_xor_sync(0xffffffffu, m, o));
    float e = expf(mylogit - m);
    float ssum = e;
#pragma unroll
    for (int o = 16; o >= 1; o >>= 1) ssum += __shfl_xor_sync(0xffffffffu, ssum, o);
    float attn = e / ssum;

    // ---- pass 2: weighted sums ----
    float av[8], hbar[8];
#pragma unroll
    for (int i = 0; i < 8; i++) { av[i] = 0.f; hbar[i] = 0.f; }
    for (int k = 0; k < 16; k++) {
        float a = __shfl_sync(0xffffffffu, attn, k);
        int idx = __ldg(kidx + k);
        float4 nb = __ldg(batpts + idx);
        float dx = px - nb.x, dy = py - nb.y, dz = pz - nb.z;
        float h[8];
#pragma unroll
        for (int i = 0; i < 8; i++) {
            float t = fmaf(dx, f1x[i], hb0[i]);
            t = fmaf(dy, f1y[i], t);
            t = fmaf(dz, f1z[i], t);
            h[i] = fmaxf(t, 0.f);
        }
        const float* vf = batQKV + (size_t)idx * 1024 + 512 + d0;
        float vv[8];
        *(float4*)(vv)     = __ldg((const float4*)vf);
        *(float4*)(vv + 4) = __ldg((const float4*)(vf + 4));
#pragma unroll
        for (int i = 0; i < 8; i++) {
            av[i]   = fmaf(a, vv[i], av[i]);
            hbar[i] = fmaf(a, h[i], hbar[i]);
        }
    }

    // write split-bf16 A' row for GEMM1: [hi(512) | hi(512) | lo(512)] bf16
    __nv_bfloat162* dst = (__nv_bfloat162*)g_Abf1 + (size_t)p * 768;
    int pb = d0 >> 1;
#pragma unroll
    for (int jj = 0; jj < 4; jj++) {
        __nv_bfloat162 hi, lo;
        split2(hbar[2 * jj], hbar[2 * jj + 1], hi, lo);
        dst[pb + jj]       = hi;
        dst[pb + jj + 256] = hi;
        dst[pb + jj + 512] = lo;
        __nv_bfloat162 hia, loa;
        split2(av[2 * jj], av[2 * jj + 1], hia, loa);
        dst[pb + jj + 128]       = hia;
        dst[pb + jj + 128 + 256] = hia;
        dst[pb + jj + 128 + 512] = loa;
    }
}

// ---------------- launch ----------------
extern "C" void kernel_launch(void* const* d_in, const int* in_sizes, int n_in,
                              void* d_out, int out_size)
{
    const float* features = (const float*)d_in[0];
    const float* xyz  = (const float*)d_in[1];
    const float* fc1w = (const float*)d_in[2];
    const float* fc1b = (const float*)d_in[3];
    const float* fc2w = (const float*)d_in[4];
    const float* fc2b = (const float*)d_in[5];
    const float* fd1w = (const float*)d_in[6];
    const float* fd1b = (const float*)d_in[7];
    const float* fd2w = (const float*)d_in[8];
    const float* fd2b = (const float*)d_in[9];
    const float* wq   = (const float*)d_in[10];
    const float* wk   = (const float*)d_in[11];
    const float* wv   = (const float*)d_in[12];
    float* out = (float*)d_out;

    prep_wc_k<<<(DPD * 768) / 256, 256>>>(fc1w, fc1b, wq, wk, wv);
    prep_qp_k<<<(DPD * 256) / 256, 256>>>(fd2w);
    prep_wo_k<<<(512 * DPD) / 256, 256>>>(fd2w, fd2b, fc2w, fc2b);
    pack_xyz_k<<<ROWS / 256, 256>>>(xyz);
    conv_feat_k<<<(ROWS * 64) / 256, 256>>>(features);
    conv_b0_k<<<(1024 * 64) / 256, 256>>>();
    conv_b1_k<<<(128 * 256) / 256, 256>>>();
    knn_kernel<<<ROWS / 8, 256>>>();

    // QKV|QP = features @ Wc + bc  (split-bf16 mma.sync)  [16384,1024]
    mma_gemm_k<0><<<dim3(8, 128), 256>>>(nullptr, nullptr);
    // attention -> split-bf16 [HBAR|AV]
    attn_kernel<<<ROWS / 8, 256>>>(fd1w, fd1b);
    // OUT = [HBAR|AV] @ Wo + bo + features -> transposed [4,128,4096]
    mma_gemm_k<1><<<dim3(1, 128), 256>>>(features, out);
}